// round 12
// baseline (speedup 1.0000x reference)
#include <cuda_runtime.h>
#include <cuda_fp16.h>
#include <math.h>
#include <stdint.h>

// ---------------------------------------------------------------- constants
#define NTOK   8192
#define HIDDEN 2048
#define NEXP   8
#define TOPK   2
#define M_TOT  (NTOK * TOPK)      // 16384
#define CAP    (M_TOT / NEXP)     // 2048
#define KDIM   2048
#define NDIM   2048

constexpr int BM = 128, BN = 128, BK = 64;
constexpr int NS = 2;                          // double-buffer ring
constexpr int NITER = KDIM / BK;               // 32
constexpr uint32_t TILE_BYTES  = 128 * 128;    // 16 KB: 128 rows x 64 fp16 (128B rows)
constexpr uint32_t OFF_A = 0;
constexpr uint32_t OFF_B = TILE_BYTES;
constexpr uint32_t STAGE_BYTES = 2 * TILE_BYTES;   // 32 KB
constexpr uint32_t SMEM_SZ     = NS * STAGE_BYTES; // 64 KB -> 3 CTAs/SM

constexpr float WSCALE    = 32.0f;             // weights pre-scaled into fp16 range
constexpr float WSCALEINV = 1.0f / 32.0f;

// ---------------------------------------------------------------- scratch
__device__ __align__(1024) __half g_xq[(size_t)M_TOT * KDIM];       // fp16(x), scattered
__device__ __align__(1024) __half g_w1q[(size_t)NEXP * NDIM * KDIM];
__device__ __align__(1024) __half g_w2q[(size_t)NEXP * NDIM * KDIM];
__device__ __align__(1024) __half g_h[(size_t)M_TOT * NDIM];        // fp16(gelu)
__device__ __align__(1024) float  g_y[(size_t)M_TOT * HIDDEN];

// ---------------------------------------------------------------- helpers
__device__ __forceinline__ uint32_t smem_u32(const void* p) {
    uint32_t a;
    asm("{ .reg .u64 t; cvta.to.shared.u64 t, %1; cvt.u32.u64 %0, t; }"
        : "=r"(a) : "l"(p));
    return a;
}
__device__ __forceinline__ uint32_t sw128(uint32_t off) {
    return off ^ ((off >> 3) & 0x70);
}
__device__ __forceinline__ void cp16(uint32_t dst, const void* src) {
    asm volatile("cp.async.cg.shared.global [%0], [%1], 16;"
                 :: "r"(dst), "l"(src));
}
__device__ __forceinline__ void cp_commit() {
    asm volatile("cp.async.commit_group;");
}
template <int N>
__device__ __forceinline__ void cp_wait() {
    asm volatile("cp.async.wait_group %0;" :: "n"(N));
}
__device__ __forceinline__ void ldsm4(uint32_t* r, uint32_t addr) {
    asm volatile("ldmatrix.sync.aligned.m8n8.x4.shared.b16 {%0,%1,%2,%3}, [%4];"
                 : "=r"(r[0]), "=r"(r[1]), "=r"(r[2]), "=r"(r[3]) : "r"(addr));
}
__device__ __forceinline__ void mma_f16(float* c, const uint32_t* a,
                                        const uint32_t* b) {
    asm volatile(
        "mma.sync.aligned.m16n8k16.row.col.f32.f16.f16.f32 "
        "{%0,%1,%2,%3},{%4,%5,%6,%7},{%8,%9},{%0,%1,%2,%3};"
        : "+f"(c[0]), "+f"(c[1]), "+f"(c[2]), "+f"(c[3])
        : "r"(a[0]), "r"(a[1]), "r"(a[2]), "r"(a[3]), "r"(b[0]), "r"(b[1]));
}

// ---------------------------------------------------------------- GEMM
// C[r,n] = (1/32) * sum_k A[r,k] * Wq[e,n,k]   (A fp16, Wq = fp16(32*w))
// 128 threads (4 warps, 2x2), warp tile 64x64; 3 CTAs/SM (NS=2, 64 KB smem).
template <bool GELU>
__global__ void __launch_bounds__(128, 3)
gemm_f16(const __half* __restrict__ A, const __half* __restrict__ Wq,
         __half* __restrict__ out_h, float* __restrict__ out_f32) {
    extern __shared__ __align__(1024) char smem[];
    const uint32_t sb = smem_u32(smem);
    const int tid  = threadIdx.x;
    const int lane = tid & 31;
    const int w    = tid >> 5;
    const int wm   = w & 1;       // M half (64 rows)
    const int wn   = w >> 1;      // N half (64 cols)
    const int grow0 = blockIdx.y * BM;
    const int gcol0 = blockIdx.x * BN;
    const int e     = grow0 / CAP;

    // ---- loader: 16 x 16B per thread per stage; 8 threads cover one 128B row
    const int ltile = tid >> 6;          // 0 = A, 1 = B
    const int lc    = tid & 7;           // 16B chunk within 128B row
    const int lr0   = (tid & 63) >> 3;   // row 0..7 (then +8 per sub-iter)
    const uint32_t soff0 = (uint32_t)ltile * TILE_BYTES +
                           sw128((uint32_t)lr0 * 128 + lc * 16);
    const __half* gsrc = (ltile == 0)
        ? A  + (size_t)(grow0 + lr0) * KDIM + lc * 8
        : Wq + ((size_t)e * NDIM + gcol0 + lr0) * KDIM + lc * 8;

    auto load_stage = [&](int it) {
        if (it < NITER) {
            const uint32_t dst = sb + (uint32_t)(it & 1) * STAGE_BYTES + soff0;
            const __half* src = gsrc + it * BK;
#pragma unroll
            for (int i = 0; i < 16; i++)
                cp16(dst + i * 1024, src + (size_t)i * 8 * KDIM);
        }
        cp_commit();
    };

    // ---- ldmatrix per-lane offsets (128B rows)
    const int ar  = lane & 15;
    const int akh = lane >> 4;
    const uint32_t aoff = sw128((uint32_t)ar * 128 + akh * 16);
    const int brn = lane & 7;
    const int bh  = (lane >> 3) & 1;
    const int bgs = lane >> 4;
    uint32_t boff[4];
#pragma unroll
    for (int j = 0; j < 4; j++) {
        const int nrow = wn * 64 + j * 16 + bgs * 8 + brn;
        boff[j] = sw128((uint32_t)nrow * 128 + bh * 16);
    }

    float acc[4][8][4];
#pragma unroll
    for (int i = 0; i < 4; i++)
#pragma unroll
        for (int j = 0; j < 8; j++)
#pragma unroll
            for (int k = 0; k < 4; k++) acc[i][j][k] = 0.f;

    load_stage(0);

    for (int it = 0; it < NITER; it++) {
        cp_wait<0>();            // stage it fully arrived
        __syncthreads();         // all warps done with stage it-1, stage it visible
        load_stage(it + 1);      // fill other buffer; overlaps consume below

        const uint32_t base = sb + (uint32_t)(it & 1) * STAGE_BYTES;
#pragma unroll
        for (int kk = 0; kk < 4; kk++) {
            const uint32_t kx = (uint32_t)kk << 5;   // 32B per k16 chunk
            uint32_t bF[8][2];
#pragma unroll
            for (int j = 0; j < 4; j++) {
                uint32_t t[4];
                ldsm4(t, base + OFF_B + (boff[j] ^ kx));
                bF[2 * j][0]     = t[0]; bF[2 * j][1]     = t[1];
                bF[2 * j + 1][0] = t[2]; bF[2 * j + 1][1] = t[3];
            }
            const uint32_t aaddr = base + OFF_A + wm * 8192 + (aoff ^ kx);
#pragma unroll
            for (int mi = 0; mi < 4; mi++) {
                uint32_t aF[4];
                ldsm4(aF, aaddr + mi * 2048);
#pragma unroll
                for (int g = 0; g < 8; g++)
                    mma_f16(acc[mi][g], aF, bF[g]);
            }
        }
    }

    // ---------------- epilogue
    const int r_in = lane >> 2;
    const int c_in = (lane & 3) * 2;
#pragma unroll
    for (int mi = 0; mi < 4; mi++) {
#pragma unroll
        for (int g = 0; g < 8; g++) {
            const int row0 = grow0 + wm * 64 + mi * 16 + r_in;
            const int col  = gcol0 + wn * 64 + g * 8 + c_in;
#pragma unroll
            for (int half = 0; half < 2; half++) {
                const int row = row0 + half * 8;
                float v0 = acc[mi][g][half * 2 + 0] * WSCALEINV;
                float v1 = acc[mi][g][half * 2 + 1] * WSCALEINV;
                const size_t off = (size_t)row * NDIM + col;
                if (GELU) {
                    v0 = 0.5f * v0 * (1.0f + erff(v0 * 0.70710678118654752f));
                    v1 = 0.5f * v1 * (1.0f + erff(v1 * 0.70710678118654752f));
                    *(__half2*)(out_h + off) =
                        __halves2half2(__float2half(v0), __float2half(v1));
                } else {
                    *(float2*)(out_f32 + off) = make_float2(v0, v1);
                }
            }
        }
    }
}

// ---------------------------------------------------------------- conversions
// Weights: wq = fp16(32*w).
__global__ void quant_w_kernel(const float* __restrict__ in,
                               __half* __restrict__ q) {
    const size_t i = (size_t)blockIdx.x * blockDim.x + threadIdx.x; // over n/4
    float4 v = ((const float4*)in)[i];
    ((__half2*)q)[2 * i]     = __halves2half2(__float2half(v.x * WSCALE),
                                              __float2half(v.y * WSCALE));
    ((__half2*)q)[2 * i + 1] = __halves2half2(__float2half(v.z * WSCALE),
                                              __float2half(v.w * WSCALE));
}

// x -> fp16, scattered to expert-sorted rows.
__global__ void scatter_q_kernel(const float* __restrict__ x,
                                 const int* __restrict__ scat,
                                 __half* __restrict__ q) {
    const int p = blockIdx.x;                 // [0, M_TOT)
    const int d = scat[p];
    const float4* src = (const float4*)(x + (size_t)(p >> 1) * HIDDEN);
    __half2* dq = (__half2*)(q + (size_t)d * HIDDEN);
    for (int c = threadIdx.x; c < HIDDEN / 4; c += blockDim.x) {
        float4 v = src[c];
        dq[2 * c]     = __halves2half2(__float2half(v.x), __float2half(v.y));
        dq[2 * c + 1] = __halves2half2(__float2half(v.z), __float2half(v.w));
    }
}

__global__ void combine_kernel(const int* __restrict__ scat, float* __restrict__ out) {
    const int idx = blockIdx.x * blockDim.x + threadIdx.x;   // NTOK * HIDDEN/4
    const int t  = idx / (HIDDEN / 4);
    const int c4 = (idx % (HIDDEN / 4)) * 4;
    const int s0 = scat[t * TOPK + 0];
    const int s1 = scat[t * TOPK + 1];
    float4 v0 = *(const float4*)(g_y + (size_t)s0 * HIDDEN + c4);
    float4 v1 = *(const float4*)(g_y + (size_t)s1 * HIDDEN + c4);
    *(float4*)(out + (size_t)t * HIDDEN + c4) =
        make_float4(v0.x + v1.x, v0.y + v1.y, v0.z + v1.z, v0.w + v1.w);
}

// ---------------------------------------------------------------- host
extern "C" void kernel_launch(void* const* d_in, const int* in_sizes, int n_in,
                              void* d_out, int out_size) {
    const float* x    = (const float*)d_in[0];
    const float* w1   = (const float*)d_in[1];
    const float* w2   = (const float*)d_in[2];
    const int*   scat = (const int*)d_in[3];
    float* out = (float*)d_out;

    void *xq, *w1q, *w2q, *hb, *yb;
    cudaGetSymbolAddress(&xq, g_xq);
    cudaGetSymbolAddress(&w1q, g_w1q);
    cudaGetSymbolAddress(&w2q, g_w2q);
    cudaGetSymbolAddress(&hb, g_h);
    cudaGetSymbolAddress(&yb, g_y);

    cudaFuncSetAttribute(gemm_f16<true>,  cudaFuncAttributeMaxDynamicSharedMemorySize,
                         (int)SMEM_SZ);
    cudaFuncSetAttribute(gemm_f16<false>, cudaFuncAttributeMaxDynamicSharedMemorySize,
                         (int)SMEM_SZ);

    // conversions
    quant_w_kernel<<<(NEXP * NDIM * KDIM) / (256 * 4), 256>>>(w1, (__half*)w1q);
    quant_w_kernel<<<(NEXP * NDIM * KDIM) / (256 * 4), 256>>>(w2, (__half*)w2q);
    scatter_q_kernel<<<M_TOT, 256>>>(x, scat, (__half*)xq);

    // fc1: x @ w1^T -> gelu -> h (fp16)
    gemm_f16<true><<<dim3(NDIM / BN, M_TOT / BM), 128, SMEM_SZ>>>(
        (const __half*)xq, (const __half*)w1q, (__half*)hb, nullptr);

    // fc2: h @ w2^T -> y (f32)
    gemm_f16<false><<<dim3(HIDDEN / BN, M_TOT / BM), 128, SMEM_SZ>>>(
        (const __half*)hb, (const __half*)w2q, nullptr, (float*)yb);

    combine_kernel<<<(NTOK * (HIDDEN / 4)) / 256, 256>>>(scat, out);
}

// round 13
// speedup vs baseline: 1.0622x; 1.0622x over previous
#include <cuda_runtime.h>
#include <cuda_fp16.h>
#include <math.h>
#include <stdint.h>

// ---------------------------------------------------------------- constants
#define NTOK   8192
#define HIDDEN 2048
#define NEXP   8
#define TOPK   2
#define M_TOT  (NTOK * TOPK)      // 16384
#define CAP    (M_TOT / NEXP)     // 2048
#define KDIM   2048
#define NDIM   2048

constexpr int BM = 128, BN = 128, BK = 64;
constexpr int NS = 3;                          // pipeline ring slots
constexpr int NITER = KDIM / BK;               // 32
constexpr uint32_t TILE_BYTES  = 128 * 128;    // 16 KB: 128 rows x 64 fp16 (128B rows)
constexpr uint32_t OFF_A = 0;
constexpr uint32_t OFF_B = TILE_BYTES;
constexpr uint32_t STAGE_BYTES = 2 * TILE_BYTES;   // 32 KB
constexpr uint32_t SMEM_SZ     = NS * STAGE_BYTES; // 96 KB

constexpr float WSCALE    = 32.0f;             // weights pre-scaled into fp16 range
constexpr float WSCALEINV = 1.0f / 32.0f;

// ---------------------------------------------------------------- scratch
__device__ __align__(1024) __half g_xq[(size_t)M_TOT * KDIM];       // fp16(x), scattered
__device__ __align__(1024) __half g_w1q[(size_t)NEXP * NDIM * KDIM];
__device__ __align__(1024) __half g_w2q[(size_t)NEXP * NDIM * KDIM];
__device__ __align__(1024) __half g_h[(size_t)M_TOT * NDIM];        // fp16(gelu)
__device__ __align__(1024) __half g_y[(size_t)M_TOT * HIDDEN];      // fp16(fc2 out)

// ---------------------------------------------------------------- helpers
__device__ __forceinline__ uint32_t smem_u32(const void* p) {
    uint32_t a;
    asm("{ .reg .u64 t; cvta.to.shared.u64 t, %1; cvt.u32.u64 %0, t; }"
        : "=r"(a) : "l"(p));
    return a;
}
__device__ __forceinline__ uint32_t sw128(uint32_t off) {
    return off ^ ((off >> 3) & 0x70);
}
__device__ __forceinline__ void cp16(uint32_t dst, const void* src) {
    asm volatile("cp.async.cg.shared.global [%0], [%1], 16;"
                 :: "r"(dst), "l"(src));
}
__device__ __forceinline__ void cp_commit() {
    asm volatile("cp.async.commit_group;");
}
template <int N>
__device__ __forceinline__ void cp_wait() {
    asm volatile("cp.async.wait_group %0;" :: "n"(N));
}
__device__ __forceinline__ void ldsm4(uint32_t* r, uint32_t addr) {
    asm volatile("ldmatrix.sync.aligned.m8n8.x4.shared.b16 {%0,%1,%2,%3}, [%4];"
                 : "=r"(r[0]), "=r"(r[1]), "=r"(r[2]), "=r"(r[3]) : "r"(addr));
}
__device__ __forceinline__ void mma_f16(float* c, const uint32_t* a,
                                        const uint32_t* b) {
    asm volatile(
        "mma.sync.aligned.m16n8k16.row.col.f32.f16.f16.f32 "
        "{%0,%1,%2,%3},{%4,%5,%6,%7},{%8,%9},{%0,%1,%2,%3};"
        : "+f"(c[0]), "+f"(c[1]), "+f"(c[2]), "+f"(c[3])
        : "r"(a[0]), "r"(a[1]), "r"(a[2]), "r"(a[3]), "r"(b[0]), "r"(b[1]));
}

// ---------------------------------------------------------------- GEMM
// C[r,n] = (1/32) * sum_k A[r,k] * Wq[e,n,k]   (A fp16, Wq = fp16(32*w))
// 128 threads (4 warps, 2x2), warp tile 64x64; output fp16 (gelu optional).
template <bool GELU>
__global__ void __launch_bounds__(128, 2)
gemm_f16(const __half* __restrict__ A, const __half* __restrict__ Wq,
         __half* __restrict__ out_h) {
    extern __shared__ __align__(1024) char smem[];
    const uint32_t sb = smem_u32(smem);
    const int tid  = threadIdx.x;
    const int lane = tid & 31;
    const int w    = tid >> 5;
    const int wm   = w & 1;       // M half (64 rows)
    const int wn   = w >> 1;      // N half (64 cols)
    const int grow0 = blockIdx.y * BM;
    const int gcol0 = blockIdx.x * BN;
    const int e     = grow0 / CAP;

    // ---- loader: 16 x 16B per thread per stage; 8 threads cover one 128B row
    const int ltile = tid >> 6;          // 0 = A, 1 = B
    const int lc    = tid & 7;           // 16B chunk within 128B row
    const int lr0   = (tid & 63) >> 3;   // row 0..7 (then +8 per sub-iter)
    const uint32_t soff0 = (uint32_t)ltile * TILE_BYTES +
                           sw128((uint32_t)lr0 * 128 + lc * 16);
    const __half* gsrc = (ltile == 0)
        ? A  + (size_t)(grow0 + lr0) * KDIM + lc * 8
        : Wq + ((size_t)e * NDIM + gcol0 + lr0) * KDIM + lc * 8;

    auto load_stage = [&](int it) {
        if (it < NITER) {
            const uint32_t dst = sb + (uint32_t)(it % NS) * STAGE_BYTES + soff0;
            const __half* src = gsrc + it * BK;
#pragma unroll
            for (int i = 0; i < 16; i++)
                cp16(dst + i * 1024, src + (size_t)i * 8 * KDIM);
        }
        cp_commit();
    };

    // ---- ldmatrix per-lane offsets (128B rows)
    const int ar  = lane & 15;
    const int akh = lane >> 4;
    const uint32_t aoff = sw128((uint32_t)ar * 128 + akh * 16);
    const int brn = lane & 7;
    const int bh  = (lane >> 3) & 1;
    const int bgs = lane >> 4;
    uint32_t boff[4];
#pragma unroll
    for (int j = 0; j < 4; j++) {
        const int nrow = wn * 64 + j * 16 + bgs * 8 + brn;
        boff[j] = sw128((uint32_t)nrow * 128 + bh * 16);
    }

    float acc[4][8][4];
#pragma unroll
    for (int i = 0; i < 4; i++)
#pragma unroll
        for (int j = 0; j < 8; j++)
#pragma unroll
            for (int k = 0; k < 4; k++) acc[i][j][k] = 0.f;

    load_stage(0);
    load_stage(1);

    for (int it = 0; it < NITER; it++) {
        cp_wait<1>();
        __syncthreads();
        const uint32_t base = sb + (uint32_t)(it % NS) * STAGE_BYTES;
        const uint32_t ab = base + OFF_A + wm * 8192;
        const uint32_t bb = base + OFF_B;

        uint32_t bF[2][8][2];   // double-buffered B fragments (per k16)
        uint32_t aF[2][4];      // double-buffered A fragments (per mi)

        // prime kk=0 fragments before issuing the long cp.async burst
#pragma unroll
        for (int j = 0; j < 4; j++) {
            uint32_t t[4];
            ldsm4(t, bb + boff[j]);
            bF[0][2 * j][0] = t[0]; bF[0][2 * j][1] = t[1];
            bF[0][2 * j + 1][0] = t[2]; bF[0][2 * j + 1][1] = t[3];
        }
        ldsm4(aF[0], ab + aoff);

        load_stage(it + 2);

#pragma unroll
        for (int kk = 0; kk < 4; kk++) {
            const int cb = kk & 1;
            const uint32_t kx = (uint32_t)kk << 5;
#pragma unroll
            for (int mi = 0; mi < 4; mi++) {
                const int ca = (kk * 4 + mi) & 1;
                // prefetch next fragments one MMA-group ahead
                if (mi < 3) {
                    ldsm4(aF[ca ^ 1], ab + (aoff ^ kx) + (mi + 1) * 2048);
                } else if (kk < 3) {
                    const uint32_t kx2 = (uint32_t)(kk + 1) << 5;
#pragma unroll
                    for (int j = 0; j < 4; j++) {
                        uint32_t t[4];
                        ldsm4(t, bb + (boff[j] ^ kx2));
                        bF[cb ^ 1][2 * j][0] = t[0]; bF[cb ^ 1][2 * j][1] = t[1];
                        bF[cb ^ 1][2 * j + 1][0] = t[2]; bF[cb ^ 1][2 * j + 1][1] = t[3];
                    }
                    ldsm4(aF[ca ^ 1], ab + (aoff ^ kx2));
                }
#pragma unroll
                for (int g = 0; g < 8; g++)
                    mma_f16(acc[mi][g], aF[ca], bF[cb][g]);
            }
        }
    }

    // ---------------- epilogue (fp16 output for both layers)
    const int r_in = lane >> 2;
    const int c_in = (lane & 3) * 2;
#pragma unroll
    for (int mi = 0; mi < 4; mi++) {
#pragma unroll
        for (int g = 0; g < 8; g++) {
            const int row0 = grow0 + wm * 64 + mi * 16 + r_in;
            const int col  = gcol0 + wn * 64 + g * 8 + c_in;
#pragma unroll
            for (int half = 0; half < 2; half++) {
                const int row = row0 + half * 8;
                float v0 = acc[mi][g][half * 2 + 0] * WSCALEINV;
                float v1 = acc[mi][g][half * 2 + 1] * WSCALEINV;
                const size_t off = (size_t)row * NDIM + col;
                if (GELU) {
                    v0 = 0.5f * v0 * (1.0f + erff(v0 * 0.70710678118654752f));
                    v1 = 0.5f * v1 * (1.0f + erff(v1 * 0.70710678118654752f));
                }
                *(__half2*)(out_h + off) =
                    __halves2half2(__float2half(v0), __float2half(v1));
            }
        }
    }
}

// ---------------------------------------------------------------- conversions
// Weights: wq = fp16(32*w).  One launch covers both weight tensors.
__global__ void quant_w_kernel(const float* __restrict__ w1,
                               const float* __restrict__ w2,
                               __half* __restrict__ q1,
                               __half* __restrict__ q2) {
    const size_t half_blocks = (size_t)(NEXP * NDIM * KDIM) / (256 * 4);
    const bool second = blockIdx.x >= half_blocks;
    const float* in = second ? w2 : w1;
    __half* q = second ? q2 : q1;
    const size_t i = (size_t)(blockIdx.x - (second ? half_blocks : 0)) * blockDim.x
                   + threadIdx.x;
    float4 v = ((const float4*)in)[i];
    ((__half2*)q)[2 * i]     = __halves2half2(__float2half(v.x * WSCALE),
                                              __float2half(v.y * WSCALE));
    ((__half2*)q)[2 * i + 1] = __halves2half2(__float2half(v.z * WSCALE),
                                              __float2half(v.w * WSCALE));
}

// x -> fp16, scattered to expert-sorted rows.
__global__ void scatter_q_kernel(const float* __restrict__ x,
                                 const int* __restrict__ scat,
                                 __half* __restrict__ q) {
    const int p = blockIdx.x;                 // [0, M_TOT)
    const int d = scat[p];
    const float4* src = (const float4*)(x + (size_t)(p >> 1) * HIDDEN);
    __half2* dq = (__half2*)(q + (size_t)d * HIDDEN);
    for (int c = threadIdx.x; c < HIDDEN / 4; c += blockDim.x) {
        float4 v = src[c];
        dq[2 * c]     = __halves2half2(__float2half(v.x), __float2half(v.y));
        dq[2 * c + 1] = __halves2half2(__float2half(v.z), __float2half(v.w));
    }
}

__global__ void combine_kernel(const int* __restrict__ scat, float* __restrict__ out) {
    const int idx = blockIdx.x * blockDim.x + threadIdx.x;   // NTOK * HIDDEN/4
    const int t  = idx / (HIDDEN / 4);
    const int c4 = (idx % (HIDDEN / 4)) * 4;
    const int s0 = scat[t * TOPK + 0];
    const int s1 = scat[t * TOPK + 1];
    const __half2* y0 = (const __half2*)(g_y + (size_t)s0 * HIDDEN + c4);
    const __half2* y1 = (const __half2*)(g_y + (size_t)s1 * HIDDEN + c4);
    float2 a0 = __half22float2(y0[0]), a1 = __half22float2(y0[1]);
    float2 b0 = __half22float2(y1[0]), b1 = __half22float2(y1[1]);
    *(float4*)(out + (size_t)t * HIDDEN + c4) =
        make_float4(a0.x + b0.x, a0.y + b0.y, a1.x + b1.x, a1.y + b1.y);
}

// ---------------------------------------------------------------- host
extern "C" void kernel_launch(void* const* d_in, const int* in_sizes, int n_in,
                              void* d_out, int out_size) {
    const float* x    = (const float*)d_in[0];
    const float* w1   = (const float*)d_in[1];
    const float* w2   = (const float*)d_in[2];
    const int*   scat = (const int*)d_in[3];
    float* out = (float*)d_out;

    void *xq, *w1q, *w2q, *hb, *yb;
    cudaGetSymbolAddress(&xq, g_xq);
    cudaGetSymbolAddress(&w1q, g_w1q);
    cudaGetSymbolAddress(&w2q, g_w2q);
    cudaGetSymbolAddress(&hb, g_h);
    cudaGetSymbolAddress(&yb, g_y);

    cudaFuncSetAttribute(gemm_f16<true>,  cudaFuncAttributeMaxDynamicSharedMemorySize,
                         (int)SMEM_SZ);
    cudaFuncSetAttribute(gemm_f16<false>, cudaFuncAttributeMaxDynamicSharedMemorySize,
                         (int)SMEM_SZ);

    // conversions (both weight tensors in one launch)
    quant_w_kernel<<<2 * (NEXP * NDIM * KDIM) / (256 * 4), 256>>>(
        w1, w2, (__half*)w1q, (__half*)w2q);
    scatter_q_kernel<<<M_TOT, 256>>>(x, scat, (__half*)xq);

    // fc1: x @ w1^T -> gelu -> h (fp16)
    gemm_f16<true><<<dim3(NDIM / BN, M_TOT / BM), 128, SMEM_SZ>>>(
        (const __half*)xq, (const __half*)w1q, (__half*)hb);

    // fc2: h @ w2^T -> y (fp16)
    gemm_f16<false><<<dim3(HIDDEN / BN, M_TOT / BM), 128, SMEM_SZ>>>(
        (const __half*)hb, (const __half*)w2q, (__half*)yb);

    combine_kernel<<<(NTOK * (HIDDEN / 4)) / 256, 256>>>(scat, out);
}

// round 14
// speedup vs baseline: 1.1465x; 1.0794x over previous
#include <cuda_runtime.h>
#include <cuda_fp16.h>
#include <math.h>
#include <stdint.h>

// ---------------------------------------------------------------- constants
#define NTOK   8192
#define HIDDEN 2048
#define NEXP   8
#define TOPK   2
#define M_TOT  (NTOK * TOPK)      // 16384
#define CAP    (M_TOT / NEXP)     // 2048
#define KDIM   2048
#define NDIM   2048

constexpr int BM = 128, BN = 128, BK = 64;
constexpr int NS = 3;                          // pipeline ring slots
constexpr int NITER = KDIM / BK;               // 32
constexpr uint32_t TILE_BYTES  = 128 * 128;    // 16 KB: 128 rows x 64 fp16 (128B rows)
constexpr uint32_t OFF_A = 0;
constexpr uint32_t OFF_B = TILE_BYTES;
constexpr uint32_t STAGE_BYTES = 2 * TILE_BYTES;   // 32 KB
constexpr uint32_t SMEM_SZ     = NS * STAGE_BYTES; // 96 KB

constexpr float WSCALE    = 32.0f;             // weights pre-scaled into fp16 range
constexpr float WSCALEINV = 1.0f / 32.0f;

// ---------------------------------------------------------------- scratch
__device__ __align__(1024) __half g_xq[(size_t)M_TOT * KDIM];       // fp16(x), scattered
__device__ __align__(1024) __half g_w1q[(size_t)NEXP * NDIM * KDIM];
__device__ __align__(1024) __half g_w2q[(size_t)NEXP * NDIM * KDIM];
__device__ __align__(1024) __half g_h[(size_t)M_TOT * NDIM];        // fp16(gelu)
__device__ __align__(1024) __half g_y[(size_t)M_TOT * HIDDEN];      // fp16(fc2 out)

// ---------------------------------------------------------------- helpers
__device__ __forceinline__ uint32_t smem_u32(const void* p) {
    uint32_t a;
    asm("{ .reg .u64 t; cvta.to.shared.u64 t, %1; cvt.u32.u64 %0, t; }"
        : "=r"(a) : "l"(p));
    return a;
}
__device__ __forceinline__ uint32_t sw128(uint32_t off) {
    return off ^ ((off >> 3) & 0x70);
}
__device__ __forceinline__ void cp16(uint32_t dst, const void* src) {
    asm volatile("cp.async.cg.shared.global [%0], [%1], 16;"
                 :: "r"(dst), "l"(src));
}
__device__ __forceinline__ void cp_commit() {
    asm volatile("cp.async.commit_group;");
}
template <int N>
__device__ __forceinline__ void cp_wait() {
    asm volatile("cp.async.wait_group %0;" :: "n"(N));
}
__device__ __forceinline__ void ldsm4(uint32_t* r, uint32_t addr) {
    asm volatile("ldmatrix.sync.aligned.m8n8.x4.shared.b16 {%0,%1,%2,%3}, [%4];"
                 : "=r"(r[0]), "=r"(r[1]), "=r"(r[2]), "=r"(r[3]) : "r"(addr));
}
__device__ __forceinline__ void mma_f16(float* c, const uint32_t* a,
                                        const uint32_t* b) {
    asm volatile(
        "mma.sync.aligned.m16n8k16.row.col.f32.f16.f16.f32 "
        "{%0,%1,%2,%3},{%4,%5,%6,%7},{%8,%9},{%0,%1,%2,%3};"
        : "+f"(c[0]), "+f"(c[1]), "+f"(c[2]), "+f"(c[3])
        : "r"(a[0]), "r"(a[1]), "r"(a[2]), "r"(a[3]), "r"(b[0]), "r"(b[1]));
}
// fast GELU: tanh form with HW tanh.approx (MUFU)
__device__ __forceinline__ float gelu_fast(float x) {
    float t = 0.7978845608028654f * x * (1.0f + 0.044715f * x * x);
    float th;
    asm("tanh.approx.f32 %0, %1;" : "=f"(th) : "f"(t));
    return 0.5f * x * (1.0f + th);
}

// ---------------------------------------------------------------- GEMM
// C[r,n] = (1/32) * sum_k A[r,k] * Wq[e,n,k]   (A fp16, Wq = fp16(32*w))
// 128 threads (4 warps, 2x2), warp tile 64x64; output fp16 (gelu optional).
template <bool GELU>
__global__ void __launch_bounds__(128, 2)
gemm_f16(const __half* __restrict__ A, const __half* __restrict__ Wq,
         __half* __restrict__ out_h) {
    extern __shared__ __align__(1024) char smem[];
    const uint32_t sb = smem_u32(smem);
    const int tid  = threadIdx.x;
    const int lane = tid & 31;
    const int w    = tid >> 5;
    const int wm   = w & 1;       // M half (64 rows)
    const int wn   = w >> 1;      // N half (64 cols)
    const int grow0 = blockIdx.y * BM;
    const int gcol0 = blockIdx.x * BN;
    const int e     = grow0 / CAP;

    // ---- loader: 16 x 16B per thread per stage; 8 threads cover one 128B row
    const int ltile = tid >> 6;          // 0 = A, 1 = B
    const int lc    = tid & 7;           // 16B chunk within 128B row
    const int lr0   = (tid & 63) >> 3;   // row 0..7 (then +8 per sub-iter)
    const uint32_t soff0 = (uint32_t)ltile * TILE_BYTES +
                           sw128((uint32_t)lr0 * 128 + lc * 16);
    const __half* gsrc = (ltile == 0)
        ? A  + (size_t)(grow0 + lr0) * KDIM + lc * 8
        : Wq + ((size_t)e * NDIM + gcol0 + lr0) * KDIM + lc * 8;

    auto load_stage = [&](int it) {
        if (it < NITER) {
            const uint32_t dst = sb + (uint32_t)(it % NS) * STAGE_BYTES + soff0;
            const __half* src = gsrc + it * BK;
#pragma unroll
            for (int i = 0; i < 16; i++)
                cp16(dst + i * 1024, src + (size_t)i * 8 * KDIM);
        }
        cp_commit();
    };

    // ---- ldmatrix per-lane offsets (128B rows)
    const int ar  = lane & 15;
    const int akh = lane >> 4;
    const uint32_t aoff = sw128((uint32_t)ar * 128 + akh * 16);
    const int brn = lane & 7;
    const int bh  = (lane >> 3) & 1;
    const int bgs = lane >> 4;
    uint32_t boff[4];
#pragma unroll
    for (int j = 0; j < 4; j++) {
        const int nrow = wn * 64 + j * 16 + bgs * 8 + brn;
        boff[j] = sw128((uint32_t)nrow * 128 + bh * 16);
    }

    float acc[4][8][4];
#pragma unroll
    for (int i = 0; i < 4; i++)
#pragma unroll
        for (int j = 0; j < 8; j++)
#pragma unroll
            for (int k = 0; k < 4; k++) acc[i][j][k] = 0.f;

    load_stage(0);
    load_stage(1);

    for (int it = 0; it < NITER; it++) {
        cp_wait<1>();
        __syncthreads();
        const uint32_t base = sb + (uint32_t)(it % NS) * STAGE_BYTES;
        const uint32_t ab = base + OFF_A + wm * 8192;
        const uint32_t bb = base + OFF_B;

        uint32_t bF[2][8][2];   // double-buffered B fragments (per k16)
        uint32_t aF[2][4];      // double-buffered A fragments (per mi)

        // prime kk=0 fragments before issuing the long cp.async burst
#pragma unroll
        for (int j = 0; j < 4; j++) {
            uint32_t t[4];
            ldsm4(t, bb + boff[j]);
            bF[0][2 * j][0] = t[0]; bF[0][2 * j][1] = t[1];
            bF[0][2 * j + 1][0] = t[2]; bF[0][2 * j + 1][1] = t[3];
        }
        ldsm4(aF[0], ab + aoff);

        load_stage(it + 2);

#pragma unroll
        for (int kk = 0; kk < 4; kk++) {
            const int cb = kk & 1;
            const uint32_t kx = (uint32_t)kk << 5;
#pragma unroll
            for (int mi = 0; mi < 4; mi++) {
                const int ca = (kk * 4 + mi) & 1;
                // prefetch next fragments one MMA-group ahead
                if (mi < 3) {
                    ldsm4(aF[ca ^ 1], ab + (aoff ^ kx) + (mi + 1) * 2048);
                } else if (kk < 3) {
                    const uint32_t kx2 = (uint32_t)(kk + 1) << 5;
#pragma unroll
                    for (int j = 0; j < 4; j++) {
                        uint32_t t[4];
                        ldsm4(t, bb + (boff[j] ^ kx2));
                        bF[cb ^ 1][2 * j][0] = t[0]; bF[cb ^ 1][2 * j][1] = t[1];
                        bF[cb ^ 1][2 * j + 1][0] = t[2]; bF[cb ^ 1][2 * j + 1][1] = t[3];
                    }
                    ldsm4(aF[ca ^ 1], ab + (aoff ^ kx2));
                }
#pragma unroll
                for (int g = 0; g < 8; g++)
                    mma_f16(acc[mi][g], aF[ca], bF[cb][g]);
            }
        }
    }

    // ---------------- epilogue (fp16 output for both layers)
    const int r_in = lane >> 2;
    const int c_in = (lane & 3) * 2;
#pragma unroll
    for (int mi = 0; mi < 4; mi++) {
#pragma unroll
        for (int g = 0; g < 8; g++) {
            const int row0 = grow0 + wm * 64 + mi * 16 + r_in;
            const int col  = gcol0 + wn * 64 + g * 8 + c_in;
#pragma unroll
            for (int half = 0; half < 2; half++) {
                const int row = row0 + half * 8;
                float v0 = acc[mi][g][half * 2 + 0] * WSCALEINV;
                float v1 = acc[mi][g][half * 2 + 1] * WSCALEINV;
                const size_t off = (size_t)row * NDIM + col;
                if (GELU) {
                    v0 = gelu_fast(v0);
                    v1 = gelu_fast(v1);
                }
                *(__half2*)(out_h + off) =
                    __halves2half2(__float2half(v0), __float2half(v1));
            }
        }
    }
}

// ---------------------------------------------------------------- conversions
// Weights: wq = fp16(32*w).  One launch covers both weight tensors.
__global__ void quant_w_kernel(const float* __restrict__ w1,
                               const float* __restrict__ w2,
                               __half* __restrict__ q1,
                               __half* __restrict__ q2) {
    const size_t half_blocks = (size_t)(NEXP * NDIM * KDIM) / (256 * 4);
    const bool second = blockIdx.x >= half_blocks;
    const float* in = second ? w2 : w1;
    __half* q = second ? q2 : q1;
    const size_t i = (size_t)(blockIdx.x - (second ? half_blocks : 0)) * blockDim.x
                   + threadIdx.x;
    float4 v = ((const float4*)in)[i];
    ((__half2*)q)[2 * i]     = __halves2half2(__float2half(v.x * WSCALE),
                                              __float2half(v.y * WSCALE));
    ((__half2*)q)[2 * i + 1] = __halves2half2(__float2half(v.z * WSCALE),
                                              __float2half(v.w * WSCALE));
}

// x -> fp16, scattered to expert-sorted rows.
__global__ void scatter_q_kernel(const float* __restrict__ x,
                                 const int* __restrict__ scat,
                                 __half* __restrict__ q) {
    const int p = blockIdx.x;                 // [0, M_TOT)
    const int d = scat[p];
    const float4* src = (const float4*)(x + (size_t)(p >> 1) * HIDDEN);
    __half2* dq = (__half2*)(q + (size_t)d * HIDDEN);
    for (int c = threadIdx.x; c < HIDDEN / 4; c += blockDim.x) {
        float4 v = src[c];
        dq[2 * c]     = __halves2half2(__float2half(v.x), __float2half(v.y));
        dq[2 * c + 1] = __halves2half2(__float2half(v.z), __float2half(v.w));
    }
}

__global__ void combine_kernel(const int* __restrict__ scat, float* __restrict__ out) {
    const int idx = blockIdx.x * blockDim.x + threadIdx.x;   // NTOK * HIDDEN/4
    const int t  = idx / (HIDDEN / 4);
    const int c4 = (idx % (HIDDEN / 4)) * 4;
    const int s0 = scat[t * TOPK + 0];
    const int s1 = scat[t * TOPK + 1];
    const __half2* y0 = (const __half2*)(g_y + (size_t)s0 * HIDDEN + c4);
    const __half2* y1 = (const __half2*)(g_y + (size_t)s1 * HIDDEN + c4);
    float2 a0 = __half22float2(y0[0]), a1 = __half22float2(y0[1]);
    float2 b0 = __half22float2(y1[0]), b1 = __half22float2(y1[1]);
    *(float4*)(out + (size_t)t * HIDDEN + c4) =
        make_float4(a0.x + b0.x, a0.y + b0.y, a1.x + b1.x, a1.y + b1.y);
}

// ---------------------------------------------------------------- host
extern "C" void kernel_launch(void* const* d_in, const int* in_sizes, int n_in,
                              void* d_out, int out_size) {
    const float* x    = (const float*)d_in[0];
    const float* w1   = (const float*)d_in[1];
    const float* w2   = (const float*)d_in[2];
    const int*   scat = (const int*)d_in[3];
    float* out = (float*)d_out;

    void *xq, *w1q, *w2q, *hb, *yb;
    cudaGetSymbolAddress(&xq, g_xq);
    cudaGetSymbolAddress(&w1q, g_w1q);
    cudaGetSymbolAddress(&w2q, g_w2q);
    cudaGetSymbolAddress(&hb, g_h);
    cudaGetSymbolAddress(&yb, g_y);

    cudaFuncSetAttribute(gemm_f16<true>,  cudaFuncAttributeMaxDynamicSharedMemorySize,
                         (int)SMEM_SZ);
    cudaFuncSetAttribute(gemm_f16<false>, cudaFuncAttributeMaxDynamicSharedMemorySize,
                         (int)SMEM_SZ);

    // conversions (both weight tensors in one launch)
    quant_w_kernel<<<2 * (NEXP * NDIM * KDIM) / (256 * 4), 256>>>(
        w1, w2, (__half*)w1q, (__half*)w2q);
    scatter_q_kernel<<<M_TOT, 256>>>(x, scat, (__half*)xq);

    // fc1: x @ w1^T -> gelu -> h (fp16)
    gemm_f16<true><<<dim3(NDIM / BN, M_TOT / BM), 128, SMEM_SZ>>>(
        (const __half*)xq, (const __half*)w1q, (__half*)hb);

    // fc2: h @ w2^T -> y (fp16)
    gemm_f16<false><<<dim3(HIDDEN / BN, M_TOT / BM), 128, SMEM_SZ>>>(
        (const __half*)hb, (const __half*)w2q, (__half*)yb);

    combine_kernel<<<(NTOK * (HIDDEN / 4)) / 256, 256>>>(scat, out);
}

// round 15
// speedup vs baseline: 1.1511x; 1.0040x over previous
#include <cuda_runtime.h>
#include <cuda_fp16.h>
#include <math.h>
#include <stdint.h>

// ---------------------------------------------------------------- constants
#define NTOK   8192
#define HIDDEN 2048
#define NEXP   8
#define TOPK   2
#define M_TOT  (NTOK * TOPK)      // 16384
#define CAP    (M_TOT / NEXP)     // 2048
#define KDIM   2048
#define NDIM   2048

constexpr int BM = 128, BN = 128, BK = 64;
constexpr int NS = 3;                          // pipeline ring slots
constexpr int NITER = KDIM / BK;               // 32
constexpr uint32_t TILE_BYTES  = 128 * 128;    // 16 KB: 128 rows x 64 fp16 (128B rows)
constexpr uint32_t OFF_A = 0;
constexpr uint32_t OFF_B = TILE_BYTES;
constexpr uint32_t STAGE_BYTES = 2 * TILE_BYTES;   // 32 KB
constexpr uint32_t SMEM_SZ     = NS * STAGE_BYTES; // 96 KB

constexpr float WSCALE    = 32.0f;             // weights pre-scaled into fp16 range
constexpr float WSCALEINV = 1.0f / 32.0f;

// ---------------------------------------------------------------- scratch
__device__ __align__(1024) __half g_xq[(size_t)M_TOT * KDIM];       // fp16(x), scattered
__device__ __align__(1024) __half g_w1q[(size_t)NEXP * NDIM * KDIM];
__device__ __align__(1024) __half g_w2q[(size_t)NEXP * NDIM * KDIM];
__device__ __align__(1024) __half g_h[(size_t)M_TOT * NDIM];        // fp16(gelu)
__device__ __align__(1024) __half g_y[(size_t)M_TOT * HIDDEN];      // fp16(fc2 out)

// ---------------------------------------------------------------- helpers
__device__ __forceinline__ uint32_t smem_u32(const void* p) {
    uint32_t a;
    asm("{ .reg .u64 t; cvta.to.shared.u64 t, %1; cvt.u32.u64 %0, t; }"
        : "=r"(a) : "l"(p));
    return a;
}
__device__ __forceinline__ uint32_t sw128(uint32_t off) {
    return off ^ ((off >> 3) & 0x70);
}
__device__ __forceinline__ void cp16(uint32_t dst, const void* src) {
    asm volatile("cp.async.cg.shared.global [%0], [%1], 16;"
                 :: "r"(dst), "l"(src));
}
__device__ __forceinline__ void cp_commit() {
    asm volatile("cp.async.commit_group;");
}
template <int N>
__device__ __forceinline__ void cp_wait() {
    asm volatile("cp.async.wait_group %0;" :: "n"(N));
}
__device__ __forceinline__ void ldsm4(uint32_t* r, uint32_t addr) {
    asm volatile("ldmatrix.sync.aligned.m8n8.x4.shared.b16 {%0,%1,%2,%3}, [%4];"
                 : "=r"(r[0]), "=r"(r[1]), "=r"(r[2]), "=r"(r[3]) : "r"(addr));
}
__device__ __forceinline__ void mma_f16(float* c, const uint32_t* a,
                                        const uint32_t* b) {
    asm volatile(
        "mma.sync.aligned.m16n8k16.row.col.f32.f16.f16.f32 "
        "{%0,%1,%2,%3},{%4,%5,%6,%7},{%8,%9},{%0,%1,%2,%3};"
        : "+f"(c[0]), "+f"(c[1]), "+f"(c[2]), "+f"(c[3])
        : "r"(a[0]), "r"(a[1]), "r"(a[2]), "r"(a[3]), "r"(b[0]), "r"(b[1]));
}
// fast GELU: tanh form with HW tanh.approx (MUFU)
__device__ __forceinline__ float gelu_fast(float x) {
    float t = 0.7978845608028654f * x * (1.0f + 0.044715f * x * x);
    float th;
    asm("tanh.approx.f32 %0, %1;" : "=f"(th) : "f"(t));
    return 0.5f * x * (1.0f + th);
}

// ---------------------------------------------------------------- GEMM
// C[r,n] = (1/32) * sum_k A[r,k] * Wq[e,n,k]   (A fp16, Wq = fp16(32*w))
// 128 threads (4 warps, 2x2), warp tile 64x64; output fp16 (gelu optional).
template <bool GELU>
__global__ void __launch_bounds__(128, 2)
gemm_f16(const __half* __restrict__ A, const __half* __restrict__ Wq,
         __half* __restrict__ out_h) {
    extern __shared__ __align__(1024) char smem[];
    const uint32_t sb = smem_u32(smem);
    const int tid  = threadIdx.x;
    const int lane = tid & 31;
    const int w    = tid >> 5;
    const int wm   = w & 1;       // M half (64 rows)
    const int wn   = w >> 1;      // N half (64 cols)
    const int grow0 = blockIdx.y * BM;
    const int gcol0 = blockIdx.x * BN;
    const int e     = grow0 / CAP;

    // ---- loader: 16 x 16B per thread per stage; 8 threads cover one 128B row
    const int ltile = tid >> 6;          // 0 = A, 1 = B
    const int lc    = tid & 7;           // 16B chunk within 128B row
    const int lr0   = (tid & 63) >> 3;   // row 0..7 (then +8 per sub-iter)
    const uint32_t soff0 = (uint32_t)ltile * TILE_BYTES +
                           sw128((uint32_t)lr0 * 128 + lc * 16);
    const __half* gsrc = (ltile == 0)
        ? A  + (size_t)(grow0 + lr0) * KDIM + lc * 8
        : Wq + ((size_t)e * NDIM + gcol0 + lr0) * KDIM + lc * 8;

    auto load_stage = [&](int it) {
        if (it < NITER) {
            const uint32_t dst = sb + (uint32_t)(it % NS) * STAGE_BYTES + soff0;
            const __half* src = gsrc + it * BK;
#pragma unroll
            for (int i = 0; i < 16; i++)
                cp16(dst + i * 1024, src + (size_t)i * 8 * KDIM);
        }
        cp_commit();
    };

    // ---- ldmatrix per-lane offsets (128B rows)
    const int ar  = lane & 15;
    const int akh = lane >> 4;
    const uint32_t aoff = sw128((uint32_t)ar * 128 + akh * 16);
    const int brn = lane & 7;
    const int bh  = (lane >> 3) & 1;
    const int bgs = lane >> 4;
    uint32_t boff[4];
#pragma unroll
    for (int j = 0; j < 4; j++) {
        const int nrow = wn * 64 + j * 16 + bgs * 8 + brn;
        boff[j] = sw128((uint32_t)nrow * 128 + bh * 16);
    }

    float acc[4][8][4];
#pragma unroll
    for (int i = 0; i < 4; i++)
#pragma unroll
        for (int j = 0; j < 8; j++)
#pragma unroll
            for (int k = 0; k < 4; k++) acc[i][j][k] = 0.f;

    load_stage(0);
    load_stage(1);

    for (int it = 0; it < NITER; it++) {
        cp_wait<1>();
        __syncthreads();
        const uint32_t base = sb + (uint32_t)(it % NS) * STAGE_BYTES;
        const uint32_t ab = base + OFF_A + wm * 8192;
        const uint32_t bb = base + OFF_B;

        uint32_t bF[2][8][2];   // double-buffered B fragments (per k16)
        uint32_t aF[2][4];      // double-buffered A fragments (per mi)

        // prime kk=0 fragments before issuing the long cp.async burst
#pragma unroll
        for (int j = 0; j < 4; j++) {
            uint32_t t[4];
            ldsm4(t, bb + boff[j]);
            bF[0][2 * j][0] = t[0]; bF[0][2 * j][1] = t[1];
            bF[0][2 * j + 1][0] = t[2]; bF[0][2 * j + 1][1] = t[3];
        }
        ldsm4(aF[0], ab + aoff);

        load_stage(it + 2);

#pragma unroll
        for (int kk = 0; kk < 4; kk++) {
            const int cb = kk & 1;
            const uint32_t kx = (uint32_t)kk << 5;
#pragma unroll
            for (int mi = 0; mi < 4; mi++) {
                const int ca = (kk * 4 + mi) & 1;
                // prefetch next fragments one MMA-group ahead
                if (mi < 3) {
                    ldsm4(aF[ca ^ 1], ab + (aoff ^ kx) + (mi + 1) * 2048);
                } else if (kk < 3) {
                    const uint32_t kx2 = (uint32_t)(kk + 1) << 5;
#pragma unroll
                    for (int j = 0; j < 4; j++) {
                        uint32_t t[4];
                        ldsm4(t, bb + (boff[j] ^ kx2));
                        bF[cb ^ 1][2 * j][0] = t[0]; bF[cb ^ 1][2 * j][1] = t[1];
                        bF[cb ^ 1][2 * j + 1][0] = t[2]; bF[cb ^ 1][2 * j + 1][1] = t[3];
                    }
                    ldsm4(aF[ca ^ 1], ab + (aoff ^ kx2));
                }
#pragma unroll
                for (int g = 0; g < 8; g++)
                    mma_f16(acc[mi][g], aF[ca], bF[cb][g]);
            }
        }
    }

    // ---------------- epilogue (fp16 output for both layers)
    const int r_in = lane >> 2;
    const int c_in = (lane & 3) * 2;
#pragma unroll
    for (int mi = 0; mi < 4; mi++) {
#pragma unroll
        for (int g = 0; g < 8; g++) {
            const int row0 = grow0 + wm * 64 + mi * 16 + r_in;
            const int col  = gcol0 + wn * 64 + g * 8 + c_in;
#pragma unroll
            for (int half = 0; half < 2; half++) {
                const int row = row0 + half * 8;
                float v0 = acc[mi][g][half * 2 + 0] * WSCALEINV;
                float v1 = acc[mi][g][half * 2 + 1] * WSCALEINV;
                const size_t off = (size_t)row * NDIM + col;
                if (GELU) {
                    v0 = gelu_fast(v0);
                    v1 = gelu_fast(v1);
                }
                *(__half2*)(out_h + off) =
                    __halves2half2(__float2half(v0), __float2half(v1));
            }
        }
    }
}

// ---------------------------------------------------------------- conversions
// Weights: wq = fp16(32*w).
__global__ void quant_w_kernel(const float* __restrict__ in,
                               __half* __restrict__ q) {
    const size_t i = (size_t)blockIdx.x * blockDim.x + threadIdx.x; // over n/4
    float4 v = ((const float4*)in)[i];
    ((__half2*)q)[2 * i]     = __halves2half2(__float2half(v.x * WSCALE),
                                              __float2half(v.y * WSCALE));
    ((__half2*)q)[2 * i + 1] = __halves2half2(__float2half(v.z * WSCALE),
                                              __float2half(v.w * WSCALE));
}

// x -> fp16, scattered to expert-sorted rows.
__global__ void scatter_q_kernel(const float* __restrict__ x,
                                 const int* __restrict__ scat,
                                 __half* __restrict__ q) {
    const int p = blockIdx.x;                 // [0, M_TOT)
    const int d = scat[p];
    const float4* src = (const float4*)(x + (size_t)(p >> 1) * HIDDEN);
    __half2* dq = (__half2*)(q + (size_t)d * HIDDEN);
    for (int c = threadIdx.x; c < HIDDEN / 4; c += blockDim.x) {
        float4 v = src[c];
        dq[2 * c]     = __halves2half2(__float2half(v.x), __float2half(v.y));
        dq[2 * c + 1] = __halves2half2(__float2half(v.z), __float2half(v.w));
    }
}

__global__ void combine_kernel(const int* __restrict__ scat, float* __restrict__ out) {
    const int idx = blockIdx.x * blockDim.x + threadIdx.x;   // NTOK * HIDDEN/4
    const int t  = idx / (HIDDEN / 4);
    const int c4 = (idx % (HIDDEN / 4)) * 4;
    const int s0 = scat[t * TOPK + 0];
    const int s1 = scat[t * TOPK + 1];
    const __half2* y0 = (const __half2*)(g_y + (size_t)s0 * HIDDEN + c4);
    const __half2* y1 = (const __half2*)(g_y + (size_t)s1 * HIDDEN + c4);
    float2 a0 = __half22float2(y0[0]), a1 = __half22float2(y0[1]);
    float2 b0 = __half22float2(y1[0]), b1 = __half22float2(y1[1]);
    *(float4*)(out + (size_t)t * HIDDEN + c4) =
        make_float4(a0.x + b0.x, a0.y + b0.y, a1.x + b1.x, a1.y + b1.y);
}

// ---------------------------------------------------------------- host
extern "C" void kernel_launch(void* const* d_in, const int* in_sizes, int n_in,
                              void* d_out, int out_size) {
    const float* x    = (const float*)d_in[0];
    const float* w1   = (const float*)d_in[1];
    const float* w2   = (const float*)d_in[2];
    const int*   scat = (const int*)d_in[3];
    float* out = (float*)d_out;

    void *xq, *w1q, *w2q, *hb, *yb;
    cudaGetSymbolAddress(&xq, g_xq);
    cudaGetSymbolAddress(&w1q, g_w1q);
    cudaGetSymbolAddress(&w2q, g_w2q);
    cudaGetSymbolAddress(&hb, g_h);
    cudaGetSymbolAddress(&yb, g_y);

    cudaFuncSetAttribute(gemm_f16<true>,  cudaFuncAttributeMaxDynamicSharedMemorySize,
                         (int)SMEM_SZ);
    cudaFuncSetAttribute(gemm_f16<false>, cudaFuncAttributeMaxDynamicSharedMemorySize,
                         (int)SMEM_SZ);

    // Fork two side streams inside the capture: scatter_q and quant(w2) run
    // concurrently with quant(w1); quant(w2) additionally overlaps GEMM1.
    // Created lazily once; creation is host-side only (no device allocation).
    static cudaStream_t s2 = nullptr, s3 = nullptr;
    static cudaEvent_t ev0 = nullptr, evB = nullptr, evC = nullptr;
    if (!s2) {
        cudaStreamCreateWithFlags(&s2, cudaStreamNonBlocking);
        cudaStreamCreateWithFlags(&s3, cudaStreamNonBlocking);
        cudaEventCreateWithFlags(&ev0, cudaEventDisableTiming);
        cudaEventCreateWithFlags(&evB, cudaEventDisableTiming);
        cudaEventCreateWithFlags(&evC, cudaEventDisableTiming);
    }

    constexpr int WBLKS = (NEXP * NDIM * KDIM) / (256 * 4);

    cudaEventRecord(ev0, 0);                   // fork point on main stream

    // side stream 2: scatter+quant x
    cudaStreamWaitEvent(s2, ev0, 0);
    scatter_q_kernel<<<M_TOT, 256, 0, s2>>>(x, scat, (__half*)xq);
    cudaEventRecord(evB, s2);

    // side stream 3: quant w2 (overlaps GEMM1 too)
    cudaStreamWaitEvent(s3, ev0, 0);
    quant_w_kernel<<<WBLKS, 256, 0, s3>>>(w2, (__half*)w2q);
    cudaEventRecord(evC, s3);

    // main: quant w1, then GEMM1 (needs w1q + xq)
    quant_w_kernel<<<WBLKS, 256>>>(w1, (__half*)w1q);
    cudaStreamWaitEvent(0, evB, 0);
    gemm_f16<true><<<dim3(NDIM / BN, M_TOT / BM), 128, SMEM_SZ>>>(
        (const __half*)xq, (const __half*)w1q, (__half*)hb);

    // GEMM2 needs w2q
    cudaStreamWaitEvent(0, evC, 0);
    gemm_f16<false><<<dim3(HIDDEN / BN, M_TOT / BM), 128, SMEM_SZ>>>(
        (const __half*)hb, (const __half*)w2q, (__half*)yb);

    combine_kernel<<<(NTOK * (HIDDEN / 4)) / 256, 256>>>(scat, out);
}